// round 13
// baseline (speedup 1.0000x reference)
#include <cuda_runtime.h>
#include <cuda_fp16.h>
#include <cstdint>
#include <math.h>

// Problem constants
#define BB 2
#define QQ 1024
#define KK 2048
#define MM 1024
#define EE 1024
#define HH 32
#define HD 32
#define LTOT (KK + MM)   // 3072
#define QSC   (0.17677669529663687f * 1.4426950408889634f)   // SCALE * log2(e)

// -------- fp16 scratch: input splits (all single) --------
__device__ __half g_q[BB*QQ*EE];
__device__ __half g_k[BB*KK*EE];
__device__ __half g_v[BB*KK*EE];
__device__ __half g_m[BB*MM*EE];
__device__ __half g_wq[EE*EE];
__device__ __half g_wk[EE*EE];
__device__ __half g_wv[EE*EE];
__device__ __half g_wo[EE*EE];

// -------- fp16 scratch: projected tensors (all single) --------
__device__ __half g_pq[BB*QQ*EE];     // pre-scaled by QSC
__device__ __half g_pk[BB*KK*EE];
__device__ __half g_pv[BB*KK*EE];
__device__ __half g_pmk[BB*MM*EE];
__device__ __half g_pmv[BB*MM*EE];
__device__ __half g_o[BB*QQ*EE];

// ============================================================
// PTX helpers
// ============================================================
__device__ __forceinline__ uint32_t smem_u32(const void* p) {
    uint32_t a;
    asm("{ .reg .u64 t; cvta.to.shared.u64 t, %1; cvt.u32.u64 %0, t; }" : "=r"(a) : "l"(p));
    return a;
}

__device__ __forceinline__ void cp_async16(uint32_t saddr, const void* gptr) {
    asm volatile("cp.async.cg.shared.global [%0], [%1], 16;" :: "r"(saddr), "l"(gptr) : "memory");
}
#define CP_COMMIT() asm volatile("cp.async.commit_group;" ::: "memory")
#define CP_WAIT(n)  asm volatile("cp.async.wait_group %0;" :: "n"(n) : "memory")

__device__ __forceinline__ void ldm_x4(uint32_t* r, uint32_t addr) {
    asm volatile("ldmatrix.sync.aligned.m8n8.x4.shared.b16 {%0,%1,%2,%3}, [%4];"
                 : "=r"(r[0]), "=r"(r[1]), "=r"(r[2]), "=r"(r[3]) : "r"(addr));
}
__device__ __forceinline__ void ldm_x4t(uint32_t* r, uint32_t addr) {
    asm volatile("ldmatrix.sync.aligned.m8n8.x4.trans.shared.b16 {%0,%1,%2,%3}, [%4];"
                 : "=r"(r[0]), "=r"(r[1]), "=r"(r[2]), "=r"(r[3]) : "r"(addr));
}

__device__ __forceinline__ void mma_f16(float* d, const uint32_t* a, const uint32_t* b) {
    asm volatile(
        "mma.sync.aligned.m16n8k16.row.col.f32.f16.f16.f32 "
        "{%0,%1,%2,%3}, {%4,%5,%6,%7}, {%8,%9}, {%0,%1,%2,%3};"
        : "+f"(d[0]), "+f"(d[1]), "+f"(d[2]), "+f"(d[3])
        : "r"(a[0]), "r"(a[1]), "r"(a[2]), "r"(a[3]), "r"(b[0]), "r"(b[1]));
}

__device__ __forceinline__ uint32_t h2ex2(uint32_t x) {
    uint32_t y;
    asm("ex2.approx.f16x2 %0, %1;" : "=r"(y) : "r"(x));
    return y;
}

__device__ __forceinline__ uint32_t pack_h2(float x0, float x1) {
    __half2 h = __floats2half2_rn(x0, x1);
    return *reinterpret_cast<uint32_t*>(&h);
}

// ============================================================
// Merged fp32 -> fp16 split (all tensors single fp16).
// ============================================================
__global__ __launch_bounds__(256) void split_all(
    const float* __restrict__ q, const float* __restrict__ k,
    const float* __restrict__ v, const float* __restrict__ m,
    const float* __restrict__ wq, const float* __restrict__ wk,
    const float* __restrict__ wv, const float* __restrict__ wo)
{
    size_t i4 = ((size_t)blockIdx.x * 256 + threadIdx.x) * 4;
    const float* src; __half* dst; size_t off;
    if      (i4 < 2097152)  { src = q;  dst = g_q;  off = i4; }
    else if (i4 < 6291456)  { src = k;  dst = g_k;  off = i4 - 2097152; }
    else if (i4 < 10485760) { src = v;  dst = g_v;  off = i4 - 6291456; }
    else if (i4 < 12582912) { src = m;  dst = g_m;  off = i4 - 10485760; }
    else if (i4 < 13631488) { src = wq; dst = g_wq; off = i4 - 12582912; }
    else if (i4 < 14680064) { src = wk; dst = g_wk; off = i4 - 13631488; }
    else if (i4 < 15728640) { src = wv; dst = g_wv; off = i4 - 14680064; }
    else                    { src = wo; dst = g_wo; off = i4 - 15728640; }
    float4 x = *(const float4*)(src + off);
    *(uint2*)(dst + off) = make_uint2(pack_h2(x.x, x.y), pack_h2(x.z, x.w));
}

// ============================================================
// Projection GEMM (NT): all single fp16, 1-pass.
// Tile 256x128, K-chunk 64, 512 threads (16 warps: 8 M x 2 N,
// warp tile 32x64), 3-stage cp.async (48KB/stage), 1 CTA/SM.
// Higher arithmetic intensity (87 FLOP/B) to stay under the
// per-SM L2-return bandwidth.
// Merged 5-projection launch: 448 tiles.
// ============================================================
#define GSTAGE 49152
#define GEMM_SMEM (3 * GSTAGE)
__global__ __launch_bounds__(512, 1) void gemm_all(
    const float* __restrict__ bq, const float* __restrict__ bk,
    const float* __restrict__ bv)
{
    extern __shared__ char smem[];
    const uint32_t sbase = smem_u32(smem);
    const int t = threadIdx.x, wid = t >> 5, lane = t & 31;
    const int warp_m = wid & 7, warp_n = wid >> 3;

    const __half *Ap, *Bp;
    const float* bias;
    __half* Ys;
    int tile_m, tile_n;
    float esc = 1.f;

    {
        int idx = blockIdx.x, local;
        if (idx < 64)       { local = idx;       Ap = g_q; Bp = g_wq; bias = bq; Ys = g_pq; esc = QSC; }
        else if (idx < 192) { local = idx - 64;  Ap = g_k; Bp = g_wk; bias = bk; Ys = g_pk; }
        else if (idx < 320) { local = idx - 192; Ap = g_v; Bp = g_wv; bias = bv; Ys = g_pv; }
        else if (idx < 384) { local = idx - 320; Ap = g_m; Bp = g_wk; bias = bk; Ys = g_pmk; }
        else                { local = idx - 384; Ap = g_m; Bp = g_wv; bias = bv; Ys = g_pmv; }
        tile_m = (local >> 3) * 256; tile_n = (local & 7) * 128;
    }

    float acc[2][8][4];
    #pragma unroll
    for (int i = 0; i < 2; i++)
        #pragma unroll
        for (int j = 0; j < 8; j++)
            #pragma unroll
            for (int kx = 0; kx < 4; kx++) acc[i][j][kx] = 0.f;

    // loader: 6 chunks of 16B per thread per stage
    // A: 256 rows x 8 chunks = 2048 slots; B: 128 rows x 8 = 1024 slots
    auto issue_stage = [&](int c, int st) {
        const uint32_t sb = sbase + st * GSTAGE;
        #pragma unroll
        for (int i = 0; i < 6; i++) {
            int slot = i * 512 + t;
            if (slot < 2048) {
                int row = slot >> 3, logc = slot & 7;
                const __half* src = Ap + (size_t)(tile_m + row) * 1024 + c * 64 + logc * 8;
                cp_async16(sb + row * 128 + ((logc ^ (row & 7)) * 16), src);
            } else {
                int w = slot - 2048;
                int row = w >> 3, logc = w & 7;
                const __half* src = Bp + (size_t)(tile_n + row) * 1024 + c * 64 + logc * 8;
                cp_async16(sb + 32768 + row * 128 + ((logc ^ (row & 7)) * 16), src);
            }
        }
        CP_COMMIT();
    };

    issue_stage(0, 0);
    issue_stage(1, 1);

    const int q = lane >> 3, li = lane & 7;

    for (int c = 0; c < 16; c++) {
        const int st = c % 3;
        if (c < 15) CP_WAIT(1); else CP_WAIT(0);
        __syncthreads();
        if (c + 2 < 16) issue_stage(c + 2, (c + 2) % 3);

        const uint32_t Ab = sbase + st * GSTAGE;
        const uint32_t Bb = Ab + 32768;

        #pragma unroll
        for (int ks = 0; ks < 4; ks++) {
            uint32_t ah[2][4], bh[8][2];
            #pragma unroll
            for (int mf = 0; mf < 2; mf++) {
                int row = warp_m * 32 + mf * 16 + (q & 1) * 8 + li;
                int lch = (ks * 2 + (q >> 1)) ^ (row & 7);
                ldm_x4(ah[mf], Ab + row * 128 + lch * 16);
            }
            #pragma unroll
            for (int p = 0; p < 4; p++) {
                int row = warp_n * 64 + p * 16 + (q >> 1) * 8 + li;
                int lch = (ks * 2 + (q & 1)) ^ (row & 7);
                uint32_t r4[4];
                ldm_x4(r4, Bb + row * 128 + lch * 16);
                bh[p * 2][0] = r4[0]; bh[p * 2][1] = r4[1];
                bh[p * 2 + 1][0] = r4[2]; bh[p * 2 + 1][1] = r4[3];
            }
            #pragma unroll
            for (int mf = 0; mf < 2; mf++)
                #pragma unroll
                for (int nf = 0; nf < 8; nf++)
                    mma_f16(acc[mf][nf], ah[mf], bh[nf]);
        }
    }

    #pragma unroll
    for (int mf = 0; mf < 2; mf++) {
        int r0 = tile_m + warp_m * 32 + mf * 16 + (lane >> 2);
        #pragma unroll
        for (int nf = 0; nf < 8; nf++) {
            int col = tile_n + warp_n * 64 + nf * 8 + (lane & 3) * 2;
            float b0 = __ldg(bias + col), b1 = __ldg(bias + col + 1);
            *(uint32_t*)(Ys + (size_t)r0 * 1024 + col) =
                pack_h2((acc[mf][nf][0] + b0) * esc, (acc[mf][nf][1] + b1) * esc);
            *(uint32_t*)(Ys + (size_t)(r0 + 8) * 1024 + col) =
                pack_h2((acc[mf][nf][2] + b0) * esc, (acc[mf][nf][3] + b1) * esc);
        }
    }
}

// ============================================================
// Output projection GEMM: tile 64x128 -> 256 CTAs (2/SM).
// 8 warps as 2(M) x 4(N); 4-stage cp.async; single barrier/chunk.
// ============================================================
#define OSTAGE 24576
#define OUT_SMEM (4 * OSTAGE)
__global__ __launch_bounds__(256, 2) void gemm_out(
    const float* __restrict__ bo, float* __restrict__ out)
{
    extern __shared__ char smem[];
    const uint32_t sbase = smem_u32(smem);
    const int t = threadIdx.x, wid = t >> 5, lane = t & 31;
    const int warp_m = wid & 1, warp_n = wid >> 1;
    const int tile_m = ((int)blockIdx.x >> 3) * 64;
    const int tile_n = ((int)blockIdx.x & 7) * 128;

    float acc[2][4][4];
    #pragma unroll
    for (int i = 0; i < 2; i++)
        #pragma unroll
        for (int j = 0; j < 4; j++)
            #pragma unroll
            for (int kx = 0; kx < 4; kx++) acc[i][j][kx] = 0.f;

    auto issue_stage = [&](int c, int st) {
        const uint32_t sb = sbase + st * OSTAGE;
        #pragma unroll
        for (int i = 0; i < 6; i++) {
            int slot = i * 256 + t;
            if (slot < 512) {
                int row = slot >> 3, logc = slot & 7;
                const __half* src = g_o + (size_t)(tile_m + row) * 1024 + c * 64 + logc * 8;
                cp_async16(sb + row * 128 + ((logc ^ (row & 7)) * 16), src);
            } else {
                int w = slot - 512;
                int row = w >> 3, logc = w & 7;
                const __half* src = g_wo + (size_t)(tile_n + row) * 1024 + c * 64 + logc * 8;
                cp_async16(sb + 8192 + row * 128 + ((logc ^ (row & 7)) * 16), src);
            }
        }
        CP_COMMIT();
    };

    issue_stage(0, 0);
    issue_stage(1, 1);
    issue_stage(2, 2);

    const int q = lane >> 3, li = lane & 7;

    for (int c = 0; c < 16; c++) {
        const int st = c & 3;
        if (c <= 13) CP_WAIT(2);
        else if (c == 14) CP_WAIT(1);
        else CP_WAIT(0);
        __syncthreads();
        if (c + 3 < 16) issue_stage(c + 3, (c + 3) & 3);

        const uint32_t Ab = sbase + st * OSTAGE;
        const uint32_t Bb = Ab + 8192;

        #pragma unroll
        for (int ks = 0; ks < 4; ks++) {
            uint32_t ah[2][4], bh[4][2];
            #pragma unroll
            for (int mf = 0; mf < 2; mf++) {
                int row = warp_m * 32 + mf * 16 + (q & 1) * 8 + li;
                int lch = (ks * 2 + (q >> 1)) ^ (row & 7);
                ldm_x4(ah[mf], Ab + row * 128 + lch * 16);
            }
            #pragma unroll
            for (int p = 0; p < 2; p++) {
                int row = warp_n * 32 + p * 16 + (q >> 1) * 8 + li;
                int lch = (ks * 2 + (q & 1)) ^ (row & 7);
                uint32_t r4[4];
                ldm_x4(r4, Bb + row * 128 + lch * 16);
                bh[p * 2][0] = r4[0]; bh[p * 2][1] = r4[1];
                bh[p * 2 + 1][0] = r4[2]; bh[p * 2 + 1][1] = r4[3];
            }
            #pragma unroll
            for (int mf = 0; mf < 2; mf++)
                #pragma unroll
                for (int nf = 0; nf < 4; nf++)
                    mma_f16(acc[mf][nf], ah[mf], bh[nf]);
        }
    }

    #pragma unroll
    for (int mf = 0; mf < 2; mf++) {
        int r0 = tile_m + warp_m * 32 + mf * 16 + (lane >> 2);
        #pragma unroll
        for (int nf = 0; nf < 4; nf++) {
            int col = tile_n + warp_n * 32 + nf * 8 + (lane & 3) * 2;
            float b0 = __ldg(bo + col), b1 = __ldg(bo + col + 1);
            *(float2*)(out + (size_t)r0 * 1024 + col) =
                make_float2(acc[mf][nf][0] + b0, acc[mf][nf][1] + b1);
            *(float2*)(out + (size_t)(r0 + 8) * 1024 + col) =
                make_float2(acc[mf][nf][2] + b0, acc[mf][nf][3] + b1);
        }
    }
}

// ============================================================
// Flash attention: fixed-max softmax, f16x2 ex2, row sums via
// ones-fragment mma. 3-stage KV ring, single barrier per tile.
// Block: 128 queries x one (b,h). Q pre-scaled by QSC (log2).
// ============================================================
#define SROW 80
#define ATTN_SMEM (10240 + 3 * 10240)
__global__ __launch_bounds__(256, 2) void attn_mma()
{
    extern __shared__ char smem[];
    const uint32_t sbase = smem_u32(smem);
    const int t = threadIdx.x, wid = t >> 5, lane = t & 31;
    const int q0 = blockIdx.x * 128;
    const int bh = blockIdx.y, b = bh >> 5, h = bh & 31;
    const int qg = lane >> 3, li = lane & 7;

    auto issue_kv_nc = [&](int kt, int st) {   // no commit
        const int l0 = kt * 64;
        size_t rb;
        const __half *s0, *s1;
        if (l0 < KK) { rb = (size_t)(b * KK + l0);        s0 = g_pk;  s1 = g_pv; }
        else         { rb = (size_t)(b * MM + (l0 - KK)); s0 = g_pmk; s1 = g_pmv; }
        uint32_t stb = sbase + 10240 + st * 10240;
        int row = t >> 2, c = t & 3;
        size_t goff = (rb + row) * EE + h * 32 + c * 8;
        uint32_t soff = stb + row * SROW + c * 16;
        cp_async16(soff,        s0 + goff);
        cp_async16(soff + 5120, s1 + goff);
    };

    // Group 0: Q (128 rows x 4 chunks) + KV tile 0
    #pragma unroll
    for (int i = 0; i < 2; i++) {
        int w2 = i * 256 + t;
        int row = w2 >> 2, c = w2 & 3;
        const __half* g = g_pq + (size_t)(b * QQ + q0 + row) * EE + h * 32 + c * 8;
        cp_async16(sbase + row * SROW + c * 16, g);
    }
    issue_kv_nc(0, 0);
    CP_COMMIT();
    // Group 1: KV tile 1
    issue_kv_nc(1, 1);
    CP_COMMIT();

    uint32_t qh[2][4];
    float oacc[4][4];
    #pragma unroll
    for (int i = 0; i < 4; i++)
        #pragma unroll
        for (int j = 0; j < 4; j++) oacc[i][j] = 0.f;
    float lacc[4] = {0.f, 0.f, 0.f, 0.f};
    const uint32_t onesb[2] = {0x3C003C00u, 0x3C003C00u};   // 1.0h x2

    for (int kt = 0; kt < LTOT / 64; kt++) {
        const int st = kt % 3;
        if (kt < LTOT / 64 - 1) CP_WAIT(1); else CP_WAIT(0);
        __syncthreads();
        if (kt + 2 < LTOT / 64) { issue_kv_nc(kt + 2, (kt + 2) % 3); CP_COMMIT(); }

        if (kt == 0) {
            #pragma unroll
            for (int ks = 0; ks < 2; ks++) {
                uint32_t a = sbase + (wid * 16 + (lane & 15)) * SROW + (ks * 2 + (lane >> 4)) * 16;
                ldm_x4(qh[ks], a);
            }
        }

        const uint32_t KB = sbase + 10240 + st * 10240;
        const uint32_t VB = KB + 5120;

        // ---- S = Q.K^T (1-pass), log2 units
        float sacc[8][4];
        #pragma unroll
        for (int i = 0; i < 8; i++)
            #pragma unroll
            for (int j = 0; j < 4; j++) sacc[i][j] = 0.f;

        #pragma unroll
        for (int ks = 0; ks < 2; ks++) {
            uint32_t kh2[8][2];
            #pragma unroll
            for (int p = 0; p < 4; p++) {
                int row = p * 16 + (qg >> 1) * 8 + li;
                uint32_t off = row * SROW + (ks * 2 + (qg & 1)) * 16;
                uint32_t r4[4];
                ldm_x4(r4, KB + off);
                kh2[p * 2][0] = r4[0]; kh2[p * 2][1] = r4[1];
                kh2[p * 2 + 1][0] = r4[2]; kh2[p * 2 + 1][1] = r4[3];
            }
            #pragma unroll
            for (int nf = 0; nf < 8; nf++)
                mma_f16(sacc[nf], qh[ks], kh2[nf]);
        }

        // ---- P = exp2(S) in f16x2; row sums via ones mma; O += P.V
        #pragma unroll
        for (int kf = 0; kf < 4; kf++) {
            uint32_t ph[4];
            ph[0] = h2ex2(pack_h2(sacc[2*kf][0],   sacc[2*kf][1]));
            ph[1] = h2ex2(pack_h2(sacc[2*kf][2],   sacc[2*kf][3]));
            ph[2] = h2ex2(pack_h2(sacc[2*kf+1][0], sacc[2*kf+1][1]));
            ph[3] = h2ex2(pack_h2(sacc[2*kf+1][2], sacc[2*kf+1][3]));

            mma_f16(lacc, ph, onesb);   // row sums

            uint32_t vh2[4][2];
            #pragma unroll
            for (int x = 0; x < 2; x++) {
                int key = kf * 16 + (qg & 1) * 8 + li;
                uint32_t off = key * SROW + (x * 2 + (qg >> 1)) * 16;
                uint32_t r4[4];
                ldm_x4t(r4, VB + off);
                vh2[x * 2][0] = r4[0]; vh2[x * 2][1] = r4[1];
                vh2[x * 2 + 1][0] = r4[2]; vh2[x * 2 + 1][1] = r4[3];
            }
            #pragma unroll
            for (int nf = 0; nf < 4; nf++)
                mma_f16(oacc[nf], ph, vh2[nf]);
        }
    }

    // ---- epilogue: normalize + single fp16 write
    float inv0 = 1.f / lacc[0], inv1 = 1.f / lacc[2];
    size_t row0 = (size_t)(b * QQ + q0 + wid * 16 + (lane >> 2)) * EE;
    size_t row1 = row0 + 8 * EE;
    int colb = h * 32 + (lane & 3) * 2;
    #pragma unroll
    for (int nf = 0; nf < 4; nf++) {
        int cc = colb + nf * 8;
        *(uint32_t*)(g_o + row0 + cc) = pack_h2(oacc[nf][0] * inv0, oacc[nf][1] * inv0);
        *(uint32_t*)(g_o + row1 + cc) = pack_h2(oacc[nf][2] * inv1, oacc[nf][3] * inv1);
    }
}

// ============================================================
// launch
// ============================================================
extern "C" void kernel_launch(void* const* d_in, const int* in_sizes, int n_in,
                              void* d_out, int out_size)
{
    const float* query  = (const float*)d_in[0];
    const float* key    = (const float*)d_in[1];
    const float* value  = (const float*)d_in[2];
    const float* memory = (const float*)d_in[3];
    const float* Wq = (const float*)d_in[4];
    const float* bq = (const float*)d_in[5];
    const float* Wk = (const float*)d_in[6];
    const float* bk = (const float*)d_in[7];
    const float* Wv = (const float*)d_in[8];
    const float* bv = (const float*)d_in[9];
    const float* Wo = (const float*)d_in[10];
    const float* bo = (const float*)d_in[11];
    float* out = (float*)d_out;

    cudaFuncSetAttribute(gemm_all, cudaFuncAttributeMaxDynamicSharedMemorySize, GEMM_SMEM);
    cudaFuncSetAttribute(gemm_out, cudaFuncAttributeMaxDynamicSharedMemorySize, OUT_SMEM);
    cudaFuncSetAttribute(attn_mma, cudaFuncAttributeMaxDynamicSharedMemorySize, ATTN_SMEM);

    // 1. All fp32 -> fp16 conversions (one launch)
    split_all<<<16384, 256>>>(query, key, value, memory, Wq, Wk, Wv, Wo);

    // 2. All 5 projection GEMMs (one merged launch, 448 tiles of 256x128)
    gemm_all<<<448, 512, GEMM_SMEM>>>(bq, bk, bv);

    // 3. Attention: grid (Q/128 = 8, B*H = 64)
    attn_mma<<<dim3(8, 64), 256, ATTN_SMEM>>>();

    // 4. Output projection -> fp32 out (256 tiles of 64x128)
    gemm_out<<<256, 256, OUT_SMEM>>>(bo, out);
}

// round 14
// speedup vs baseline: 1.0749x; 1.0749x over previous
#include <cuda_runtime.h>
#include <cuda_fp16.h>
#include <cstdint>
#include <math.h>

// Problem constants
#define BB 2
#define QQ 1024
#define KK 2048
#define MM 1024
#define EE 1024
#define HH 32
#define HD 32
#define LTOT (KK + MM)   // 3072
#define QSC   (0.17677669529663687f * 1.4426950408889634f)   // SCALE * log2(e)

// -------- fp16 scratch: input splits (all single) --------
__device__ __half g_q[BB*QQ*EE];
__device__ __half g_k[BB*KK*EE];
__device__ __half g_v[BB*KK*EE];
__device__ __half g_m[BB*MM*EE];
__device__ __half g_wq[EE*EE];
__device__ __half g_wk[EE*EE];
__device__ __half g_wv[EE*EE];
__device__ __half g_wo[EE*EE];

// -------- fp16 scratch: projected tensors (all single) --------
__device__ __half g_pq[BB*QQ*EE];     // pre-scaled by QSC
__device__ __half g_pk[BB*KK*EE];
__device__ __half g_pv[BB*KK*EE];
__device__ __half g_pmk[BB*MM*EE];
__device__ __half g_pmv[BB*MM*EE];
__device__ __half g_o[BB*QQ*EE];

// ============================================================
// PTX helpers
// ============================================================
__device__ __forceinline__ uint32_t smem_u32(const void* p) {
    uint32_t a;
    asm("{ .reg .u64 t; cvta.to.shared.u64 t, %1; cvt.u32.u64 %0, t; }" : "=r"(a) : "l"(p));
    return a;
}

__device__ __forceinline__ void cp_async16(uint32_t saddr, const void* gptr) {
    asm volatile("cp.async.cg.shared.global [%0], [%1], 16;" :: "r"(saddr), "l"(gptr) : "memory");
}
#define CP_COMMIT() asm volatile("cp.async.commit_group;" ::: "memory")
#define CP_WAIT(n)  asm volatile("cp.async.wait_group %0;" :: "n"(n) : "memory")

__device__ __forceinline__ void ldm_x4(uint32_t* r, uint32_t addr) {
    asm volatile("ldmatrix.sync.aligned.m8n8.x4.shared.b16 {%0,%1,%2,%3}, [%4];"
                 : "=r"(r[0]), "=r"(r[1]), "=r"(r[2]), "=r"(r[3]) : "r"(addr));
}
__device__ __forceinline__ void ldm_x4t(uint32_t* r, uint32_t addr) {
    asm volatile("ldmatrix.sync.aligned.m8n8.x4.trans.shared.b16 {%0,%1,%2,%3}, [%4];"
                 : "=r"(r[0]), "=r"(r[1]), "=r"(r[2]), "=r"(r[3]) : "r"(addr));
}

__device__ __forceinline__ void mma_f16(float* d, const uint32_t* a, const uint32_t* b) {
    asm volatile(
        "mma.sync.aligned.m16n8k16.row.col.f32.f16.f16.f32 "
        "{%0,%1,%2,%3}, {%4,%5,%6,%7}, {%8,%9}, {%0,%1,%2,%3};"
        : "+f"(d[0]), "+f"(d[1]), "+f"(d[2]), "+f"(d[3])
        : "r"(a[0]), "r"(a[1]), "r"(a[2]), "r"(a[3]), "r"(b[0]), "r"(b[1]));
}

__device__ __forceinline__ uint32_t h2ex2(uint32_t x) {
    uint32_t y;
    asm("ex2.approx.f16x2 %0, %1;" : "=r"(y) : "r"(x));
    return y;
}

__device__ __forceinline__ uint32_t pack_h2(float x0, float x1) {
    __half2 h = __floats2half2_rn(x0, x1);
    return *reinterpret_cast<uint32_t*>(&h);
}

// ============================================================
// Merged fp32 -> fp16 split (all tensors single fp16).
// ============================================================
__global__ __launch_bounds__(256) void split_all(
    const float* __restrict__ q, const float* __restrict__ k,
    const float* __restrict__ v, const float* __restrict__ m,
    const float* __restrict__ wq, const float* __restrict__ wk,
    const float* __restrict__ wv, const float* __restrict__ wo)
{
    size_t i4 = ((size_t)blockIdx.x * 256 + threadIdx.x) * 4;
    const float* src; __half* dst; size_t off;
    if      (i4 < 2097152)  { src = q;  dst = g_q;  off = i4; }
    else if (i4 < 6291456)  { src = k;  dst = g_k;  off = i4 - 2097152; }
    else if (i4 < 10485760) { src = v;  dst = g_v;  off = i4 - 6291456; }
    else if (i4 < 12582912) { src = m;  dst = g_m;  off = i4 - 10485760; }
    else if (i4 < 13631488) { src = wq; dst = g_wq; off = i4 - 12582912; }
    else if (i4 < 14680064) { src = wk; dst = g_wk; off = i4 - 13631488; }
    else if (i4 < 15728640) { src = wv; dst = g_wv; off = i4 - 14680064; }
    else                    { src = wo; dst = g_wo; off = i4 - 15728640; }
    float4 x = *(const float4*)(src + off);
    *(uint2*)(dst + off) = make_uint2(pack_h2(x.x, x.y), pack_h2(x.z, x.w));
}

// ============================================================
// Projection GEMM (NT): all single fp16, 1-pass. Tile 128x128,
// K-chunk 64, 256 threads (8 warps 4x2), 3-stage, 2 CTAs/SM.
// (Best-measured config, R11.)
// ============================================================
#define GSTAGE 32768
#define GEMM_SMEM (3 * GSTAGE)
__global__ __launch_bounds__(256, 2) void gemm_all(
    const float* __restrict__ bq, const float* __restrict__ bk,
    const float* __restrict__ bv)
{
    extern __shared__ char smem[];
    const uint32_t sbase = smem_u32(smem);
    const int t = threadIdx.x, wid = t >> 5, lane = t & 31;
    const int warp_m = wid & 3, warp_n = wid >> 2;

    const __half *Ap, *Bp;
    const float* bias;
    __half* Ys;
    int tile_m, tile_n;
    float esc = 1.f;

    {
        int idx = blockIdx.x, local;
        if (idx < 128)      { local = idx;       Ap = g_q; Bp = g_wq; bias = bq; Ys = g_pq; esc = QSC; }
        else if (idx < 384) { local = idx - 128; Ap = g_k; Bp = g_wk; bias = bk; Ys = g_pk; }
        else if (idx < 640) { local = idx - 384; Ap = g_v; Bp = g_wv; bias = bv; Ys = g_pv; }
        else if (idx < 768) { local = idx - 640; Ap = g_m; Bp = g_wk; bias = bk; Ys = g_pmk; }
        else                { local = idx - 768; Ap = g_m; Bp = g_wv; bias = bv; Ys = g_pmv; }
        tile_m = (local >> 3) * 128; tile_n = (local & 7) * 128;
    }

    float acc[2][8][4];
    #pragma unroll
    for (int i = 0; i < 2; i++)
        #pragma unroll
        for (int j = 0; j < 8; j++)
            #pragma unroll
            for (int kx = 0; kx < 4; kx++) acc[i][j][kx] = 0.f;

    auto issue_stage = [&](int c, int st) {
        const uint32_t sb = sbase + st * GSTAGE;
        #pragma unroll
        for (int i = 0; i < 8; i++) {
            int slot = i * 256 + t;
            int buf = slot >> 10;
            int w = slot & 1023;
            int row = w >> 3, logc = w & 7;
            const __half* src = (buf ? Bp + (size_t)(tile_n + row) * 1024
                                     : Ap + (size_t)(tile_m + row) * 1024) + c * 64 + logc * 8;
            cp_async16(sb + buf * 16384 + row * 128 + ((logc ^ (row & 7)) * 16), src);
        }
        CP_COMMIT();
    };

    issue_stage(0, 0);
    issue_stage(1, 1);

    const int q = lane >> 3, li = lane & 7;

    for (int c = 0; c < 16; c++) {
        const int st = c % 3;
        if (c < 15) CP_WAIT(1); else CP_WAIT(0);
        __syncthreads();
        if (c + 2 < 16) issue_stage(c + 2, (c + 2) % 3);

        const uint32_t Ab = sbase + st * GSTAGE;
        const uint32_t Bb = Ab + 16384;

        #pragma unroll
        for (int ks = 0; ks < 4; ks++) {
            uint32_t ah[2][4], bh[8][2];
            #pragma unroll
            for (int mf = 0; mf < 2; mf++) {
                int row = warp_m * 32 + mf * 16 + (q & 1) * 8 + li;
                int lch = (ks * 2 + (q >> 1)) ^ (row & 7);
                ldm_x4(ah[mf], Ab + row * 128 + lch * 16);
            }
            #pragma unroll
            for (int p = 0; p < 4; p++) {
                int row = warp_n * 64 + p * 16 + (q >> 1) * 8 + li;
                int lch = (ks * 2 + (q & 1)) ^ (row & 7);
                uint32_t r4[4];
                ldm_x4(r4, Bb + row * 128 + lch * 16);
                bh[p * 2][0] = r4[0]; bh[p * 2][1] = r4[1];
                bh[p * 2 + 1][0] = r4[2]; bh[p * 2 + 1][1] = r4[3];
            }
            #pragma unroll
            for (int mf = 0; mf < 2; mf++)
                #pragma unroll
                for (int nf = 0; nf < 8; nf++)
                    mma_f16(acc[mf][nf], ah[mf], bh[nf]);
        }
    }

    #pragma unroll
    for (int mf = 0; mf < 2; mf++) {
        int r0 = tile_m + warp_m * 32 + mf * 16 + (lane >> 2);
        #pragma unroll
        for (int nf = 0; nf < 8; nf++) {
            int col = tile_n + warp_n * 64 + nf * 8 + (lane & 3) * 2;
            float b0 = __ldg(bias + col), b1 = __ldg(bias + col + 1);
            *(uint32_t*)(Ys + (size_t)r0 * 1024 + col) =
                pack_h2((acc[mf][nf][0] + b0) * esc, (acc[mf][nf][1] + b1) * esc);
            *(uint32_t*)(Ys + (size_t)(r0 + 8) * 1024 + col) =
                pack_h2((acc[mf][nf][2] + b0) * esc, (acc[mf][nf][3] + b1) * esc);
        }
    }
}

// ============================================================
// Output projection GEMM: tile 64x128 -> 256 CTAs (2/SM).
// ============================================================
#define OSTAGE 24576
#define OUT_SMEM (4 * OSTAGE)
__global__ __launch_bounds__(256, 2) void gemm_out(
    const float* __restrict__ bo, float* __restrict__ out)
{
    extern __shared__ char smem[];
    const uint32_t sbase = smem_u32(smem);
    const int t = threadIdx.x, wid = t >> 5, lane = t & 31;
    const int warp_m = wid & 1, warp_n = wid >> 1;
    const int tile_m = ((int)blockIdx.x >> 3) * 64;
    const int tile_n = ((int)blockIdx.x & 7) * 128;

    float acc[2][4][4];
    #pragma unroll
    for (int i = 0; i < 2; i++)
        #pragma unroll
        for (int j = 0; j < 4; j++)
            #pragma unroll
            for (int kx = 0; kx < 4; kx++) acc[i][j][kx] = 0.f;

    auto issue_stage = [&](int c, int st) {
        const uint32_t sb = sbase + st * OSTAGE;
        #pragma unroll
        for (int i = 0; i < 6; i++) {
            int slot = i * 256 + t;
            if (slot < 512) {
                int row = slot >> 3, logc = slot & 7;
                const __half* src = g_o + (size_t)(tile_m + row) * 1024 + c * 64 + logc * 8;
                cp_async16(sb + row * 128 + ((logc ^ (row & 7)) * 16), src);
            } else {
                int w = slot - 512;
                int row = w >> 3, logc = w & 7;
                const __half* src = g_wo + (size_t)(tile_n + row) * 1024 + c * 64 + logc * 8;
                cp_async16(sb + 8192 + row * 128 + ((logc ^ (row & 7)) * 16), src);
            }
        }
        CP_COMMIT();
    };

    issue_stage(0, 0);
    issue_stage(1, 1);
    issue_stage(2, 2);

    const int q = lane >> 3, li = lane & 7;

    for (int c = 0; c < 16; c++) {
        const int st = c & 3;
        if (c <= 13) CP_WAIT(2);
        else if (c == 14) CP_WAIT(1);
        else CP_WAIT(0);
        __syncthreads();
        if (c + 3 < 16) issue_stage(c + 3, (c + 3) & 3);

        const uint32_t Ab = sbase + st * OSTAGE;
        const uint32_t Bb = Ab + 8192;

        #pragma unroll
        for (int ks = 0; ks < 4; ks++) {
            uint32_t ah[2][4], bh[4][2];
            #pragma unroll
            for (int mf = 0; mf < 2; mf++) {
                int row = warp_m * 32 + mf * 16 + (q & 1) * 8 + li;
                int lch = (ks * 2 + (q >> 1)) ^ (row & 7);
                ldm_x4(ah[mf], Ab + row * 128 + lch * 16);
            }
            #pragma unroll
            for (int p = 0; p < 2; p++) {
                int row = warp_n * 32 + p * 16 + (q >> 1) * 8 + li;
                int lch = (ks * 2 + (q & 1)) ^ (row & 7);
                uint32_t r4[4];
                ldm_x4(r4, Bb + row * 128 + lch * 16);
                bh[p * 2][0] = r4[0]; bh[p * 2][1] = r4[1];
                bh[p * 2 + 1][0] = r4[2]; bh[p * 2 + 1][1] = r4[3];
            }
            #pragma unroll
            for (int mf = 0; mf < 2; mf++)
                #pragma unroll
                for (int nf = 0; nf < 4; nf++)
                    mma_f16(acc[mf][nf], ah[mf], bh[nf]);
        }
    }

    #pragma unroll
    for (int mf = 0; mf < 2; mf++) {
        int r0 = tile_m + warp_m * 32 + mf * 16 + (lane >> 2);
        #pragma unroll
        for (int nf = 0; nf < 4; nf++) {
            int col = tile_n + warp_n * 32 + nf * 8 + (lane & 3) * 2;
            float b0 = __ldg(bo + col), b1 = __ldg(bo + col + 1);
            *(float2*)(out + (size_t)r0 * 1024 + col) =
                make_float2(acc[mf][nf][0] + b0, acc[mf][nf][1] + b1);
            *(float2*)(out + (size_t)(r0 + 8) * 1024 + col) =
                make_float2(acc[mf][nf][2] + b0, acc[mf][nf][3] + b1);
        }
    }
}

// ============================================================
// Flash attention: Q-tile 256 rows, 512 threads (16 warps x 16
// rows), 3-stage KV ring, streamed softmax (per-kf S->ex2->PV)
// to fit 64 regs. Fixed-max, f16x2 ex2, ones-mma row sums.
// Grid 256 CTAs -> single wave at 2 CTAs/SM (32 warps/SM).
// Smem: Q 256x80B (20480) + 3 x {K,V} (10240 each).
// ============================================================
#define SROW 80
#define ATTN_SMEM (20480 + 3 * 10240)
__global__ __launch_bounds__(512, 2) void attn_mma()
{
    extern __shared__ char smem[];
    const uint32_t sbase = smem_u32(smem);
    const int t = threadIdx.x, wid = t >> 5, lane = t & 31;
    const int q0 = blockIdx.x * 256;
    const int bh = blockIdx.y, b = bh >> 5, h = bh & 31;
    const int qg = lane >> 3, li = lane & 7;

    auto issue_kv_nc = [&](int kt, int st) {   // 1 cp.async per thread
        const int l0 = kt * 64;
        size_t rb;
        const __half *s0, *s1;
        if (l0 < KK) { rb = (size_t)(b * KK + l0);        s0 = g_pk;  s1 = g_pv; }
        else         { rb = (size_t)(b * MM + (l0 - KK)); s0 = g_pmk; s1 = g_pmv; }
        uint32_t stb = sbase + 20480 + st * 10240;
        int tens = t >> 8;              // 0 = K, 1 = V
        int row = (t >> 2) & 63, c = t & 3;
        size_t goff = (rb + row) * EE + h * 32 + c * 8;
        cp_async16(stb + tens * 5120 + row * SROW + c * 16,
                   (tens ? s1 : s0) + goff);
    };

    // Group 0: Q (256 rows x 4 chunks = 1024 -> 2/thread) + KV tile 0
    #pragma unroll
    for (int i = 0; i < 2; i++) {
        int w2 = i * 512 + t;
        int row = w2 >> 2, c = w2 & 3;
        const __half* g = g_pq + (size_t)(b * QQ + q0 + row) * EE + h * 32 + c * 8;
        cp_async16(sbase + row * SROW + c * 16, g);
    }
    issue_kv_nc(0, 0);
    CP_COMMIT();
    issue_kv_nc(1, 1);
    CP_COMMIT();

    uint32_t qh[2][4];
    float oacc[4][4];
    #pragma unroll
    for (int i = 0; i < 4; i++)
        #pragma unroll
        for (int j = 0; j < 4; j++) oacc[i][j] = 0.f;
    float lacc[4] = {0.f, 0.f, 0.f, 0.f};
    const uint32_t onesb[2] = {0x3C003C00u, 0x3C003C00u};   // 1.0h x2

    for (int kt = 0; kt < LTOT / 64; kt++) {
        const int st = kt % 3;
        if (kt < LTOT / 64 - 1) CP_WAIT(1); else CP_WAIT(0);
        __syncthreads();
        if (kt + 2 < LTOT / 64) { issue_kv_nc(kt + 2, (kt + 2) % 3); CP_COMMIT(); }

        if (kt == 0) {
            #pragma unroll
            for (int ks = 0; ks < 2; ks++) {
                uint32_t a = sbase + (wid * 16 + (lane & 15)) * SROW + (ks * 2 + (lane >> 4)) * 16;
                ldm_x4(qh[ks], a);
            }
        }

        const uint32_t KB = sbase + 20480 + st * 10240;
        const uint32_t VB = KB + 5120;

        // ---- streamed: per kf pair of nf, S -> exp2 -> row-sum -> PV
        #pragma unroll
        for (int p = 0; p < 4; p++) {
            // K frags for nf {2p, 2p+1}, both ks
            uint32_t kh[2][4];
            #pragma unroll
            for (int ks = 0; ks < 2; ks++) {
                int row = p * 16 + (qg >> 1) * 8 + li;
                uint32_t off = row * SROW + (ks * 2 + (qg & 1)) * 16;
                ldm_x4(kh[ks], KB + off);
            }
            float sl[2][4];
            #pragma unroll
            for (int j = 0; j < 4; j++) { sl[0][j] = 0.f; sl[1][j] = 0.f; }
            #pragma unroll
            for (int ks = 0; ks < 2; ks++) {
                mma_f16(sl[0], qh[ks], kh[ks]);       // nf = 2p  (regs 0,1)
                mma_f16(sl[1], qh[ks], kh[ks] + 2);   // nf = 2p+1
            }

            uint32_t ph[4];
            ph[0] = h2ex2(pack_h2(sl[0][0], sl[0][1]));
            ph[1] = h2ex2(pack_h2(sl[0][2], sl[0][3]));
            ph[2] = h2ex2(pack_h2(sl[1][0], sl[1][1]));
            ph[3] = h2ex2(pack_h2(sl[1][2], sl[1][3]));

            mma_f16(lacc, ph, onesb);   // row sums

            uint32_t vh[4][2];
            #pragma unroll
            for (int x = 0; x < 2; x++) {
                int key = p * 16 + (qg & 1) * 8 + li;
                uint32_t off = key * SROW + (x * 2 + (qg >> 1)) * 16;
                uint32_t r4[4];
                ldm_x4t(r4, VB + off);
                vh[x * 2][0] = r4[0]; vh[x * 2][1] = r4[1];
                vh[x * 2 + 1][0] = r4[2]; vh[x * 2 + 1][1] = r4[3];
            }
            #pragma unroll
            for (int nf = 0; nf < 4; nf++)
                mma_f16(oacc[nf], ph, vh[nf]);
        }
    }

    // ---- epilogue: normalize + single fp16 write
    float inv0 = 1.f / lacc[0], inv1 = 1.f / lacc[2];
    size_t row0 = (size_t)(b * QQ + q0 + wid * 16 + (lane >> 2)) * EE;
    size_t row1 = row0 + 8 * EE;
    int colb = h * 32 + (lane & 3) * 2;
    #pragma unroll
    for (int nf = 0; nf < 4; nf++) {
        int cc = colb + nf * 8;
        *(uint32_t*)(g_o + row0 + cc) = pack_h2(oacc[nf][0] * inv0, oacc[nf][1] * inv0);
        *(uint32_t*)(g_o + row1 + cc) = pack_h2(oacc[nf][2] * inv1, oacc[nf][3] * inv1);
    }
}

// ============================================================
// launch
// ============================================================
extern "C" void kernel_launch(void* const* d_in, const int* in_sizes, int n_in,
                              void* d_out, int out_size)
{
    const float* query  = (const float*)d_in[0];
    const float* key    = (const float*)d_in[1];
    const float* value  = (const float*)d_in[2];
    const float* memory = (const float*)d_in[3];
    const float* Wq = (const float*)d_in[4];
    const float* bq = (const float*)d_in[5];
    const float* Wk = (const float*)d_in[6];
    const float* bk = (const float*)d_in[7];
    const float* Wv = (const float*)d_in[8];
    const float* bv = (const float*)d_in[9];
    const float* Wo = (const float*)d_in[10];
    const float* bo = (const float*)d_in[11];
    float* out = (float*)d_out;

    cudaFuncSetAttribute(gemm_all, cudaFuncAttributeMaxDynamicSharedMemorySize, GEMM_SMEM);
    cudaFuncSetAttribute(gemm_out, cudaFuncAttributeMaxDynamicSharedMemorySize, OUT_SMEM);
    cudaFuncSetAttribute(attn_mma, cudaFuncAttributeMaxDynamicSharedMemorySize, ATTN_SMEM);

    // 1. All fp32 -> fp16 conversions (one launch)
    split_all<<<16384, 256>>>(query, key, value, memory, Wq, Wk, Wv, Wo);

    // 2. All 5 projection GEMMs (one merged launch, 896 tiles of 128x128)
    gemm_all<<<896, 256, GEMM_SMEM>>>(bq, bk, bv);

    // 3. Attention: grid (Q/256 = 4, B*H = 64) -> 256 CTAs, single wave
    attn_mma<<<dim3(4, 64), 512, ATTN_SMEM>>>();

    // 4. Output projection -> fp32 out (256 tiles of 64x128)
    gemm_out<<<256, 256, OUT_SMEM>>>(bo, out);
}

// round 15
// speedup vs baseline: 1.1208x; 1.0427x over previous
#include <cuda_runtime.h>
#include <cuda_fp16.h>
#include <cstdint>
#include <math.h>

// Problem constants
#define BB 2
#define QQ 1024
#define KK 2048
#define MM 1024
#define EE 1024
#define HH 32
#define HD 32
#define LTOT (KK + MM)   // 3072
#define QSC   (0.17677669529663687f * 1.4426950408889634f)   // SCALE * log2(e)

// -------- fp16 scratch: input splits (all single) --------
__device__ __half g_q[BB*QQ*EE];
__device__ __half g_k[BB*KK*EE];
__device__ __half g_v[BB*KK*EE];
__device__ __half g_m[BB*MM*EE];
__device__ __half g_wq[EE*EE];
__device__ __half g_wk[EE*EE];
__device__ __half g_wv[EE*EE];
__device__ __half g_wo[EE*EE];

// -------- fp16 scratch: projected tensors (all single) --------
__device__ __half g_pq[BB*QQ*EE];     // pre-scaled by QSC
__device__ __half g_pk[BB*KK*EE];
__device__ __half g_pv[BB*KK*EE];
__device__ __half g_pmk[BB*MM*EE];
__device__ __half g_pmv[BB*MM*EE];
__device__ __half g_o[BB*QQ*EE];

// ============================================================
// PTX helpers
// ============================================================
__device__ __forceinline__ uint32_t smem_u32(const void* p) {
    uint32_t a;
    asm("{ .reg .u64 t; cvta.to.shared.u64 t, %1; cvt.u32.u64 %0, t; }" : "=r"(a) : "l"(p));
    return a;
}

__device__ __forceinline__ void cp_async16(uint32_t saddr, const void* gptr) {
    asm volatile("cp.async.cg.shared.global [%0], [%1], 16;" :: "r"(saddr), "l"(gptr) : "memory");
}
#define CP_COMMIT() asm volatile("cp.async.commit_group;" ::: "memory")
#define CP_WAIT(n)  asm volatile("cp.async.wait_group %0;" :: "n"(n) : "memory")

__device__ __forceinline__ void ldm_x4(uint32_t* r, uint32_t addr) {
    asm volatile("ldmatrix.sync.aligned.m8n8.x4.shared.b16 {%0,%1,%2,%3}, [%4];"
                 : "=r"(r[0]), "=r"(r[1]), "=r"(r[2]), "=r"(r[3]) : "r"(addr));
}
__device__ __forceinline__ void ldm_x4t(uint32_t* r, uint32_t addr) {
    asm volatile("ldmatrix.sync.aligned.m8n8.x4.trans.shared.b16 {%0,%1,%2,%3}, [%4];"
                 : "=r"(r[0]), "=r"(r[1]), "=r"(r[2]), "=r"(r[3]) : "r"(addr));
}

__device__ __forceinline__ void mma_f16(float* d, const uint32_t* a, const uint32_t* b) {
    asm volatile(
        "mma.sync.aligned.m16n8k16.row.col.f32.f16.f16.f32 "
        "{%0,%1,%2,%3}, {%4,%5,%6,%7}, {%8,%9}, {%0,%1,%2,%3};"
        : "+f"(d[0]), "+f"(d[1]), "+f"(d[2]), "+f"(d[3])
        : "r"(a[0]), "r"(a[1]), "r"(a[2]), "r"(a[3]), "r"(b[0]), "r"(b[1]));
}

__device__ __forceinline__ uint32_t h2ex2(uint32_t x) {
    uint32_t y;
    asm("ex2.approx.f16x2 %0, %1;" : "=r"(y) : "r"(x));
    return y;
}

__device__ __forceinline__ uint32_t pack_h2(float x0, float x1) {
    __half2 h = __floats2half2_rn(x0, x1);
    return *reinterpret_cast<uint32_t*>(&h);
}

// ============================================================
// Merged fp32 -> fp16 split (all tensors single fp16).
// ============================================================
__global__ __launch_bounds__(256) void split_all(
    const float* __restrict__ q, const float* __restrict__ k,
    const float* __restrict__ v, const float* __restrict__ m,
    const float* __restrict__ wq, const float* __restrict__ wk,
    const float* __restrict__ wv, const float* __restrict__ wo)
{
    size_t i4 = ((size_t)blockIdx.x * 256 + threadIdx.x) * 4;
    const float* src; __half* dst; size_t off;
    if      (i4 < 2097152)  { src = q;  dst = g_q;  off = i4; }
    else if (i4 < 6291456)  { src = k;  dst = g_k;  off = i4 - 2097152; }
    else if (i4 < 10485760) { src = v;  dst = g_v;  off = i4 - 6291456; }
    else if (i4 < 12582912) { src = m;  dst = g_m;  off = i4 - 10485760; }
    else if (i4 < 13631488) { src = wq; dst = g_wq; off = i4 - 12582912; }
    else if (i4 < 14680064) { src = wk; dst = g_wk; off = i4 - 13631488; }
    else if (i4 < 15728640) { src = wv; dst = g_wv; off = i4 - 14680064; }
    else                    { src = wo; dst = g_wo; off = i4 - 15728640; }
    float4 x = *(const float4*)(src + off);
    *(uint2*)(dst + off) = make_uint2(pack_h2(x.x, x.y), pack_h2(x.z, x.w));
}

// ============================================================
// HMMA GEMM (NT): all single fp16, 1-pass. Tile 128x128,
// K-chunk 64, 128 threads (4 warps 2x2, warp tile 64x64 ->
// 128 acc regs), 3-stage cp.async (32KB/stage), 2 CTAs/SM.
// Fragment reuse 2x for both A and B: smem crossbar demand
// 96 B/cyc < 128 -> mma-bound.
// mode 0: merged 5-projection launch (896 tiles, fp16 out).
// mode 1: out-proj (128 tiles, fp32 out).
// ============================================================
#define GSTAGE 32768
#define GEMM_SMEM (3 * GSTAGE)
__global__ __launch_bounds__(128, 2) void gemm_all(
    int mode, const float* __restrict__ bq, const float* __restrict__ bk,
    const float* __restrict__ bv, const float* __restrict__ bo,
    float* __restrict__ out)
{
    extern __shared__ char smem[];
    const uint32_t sbase = smem_u32(smem);
    const int t = threadIdx.x, wid = t >> 5, lane = t & 31;
    const int warp_m = wid & 1, warp_n = wid >> 1;

    const __half *Ap, *Bp;
    const float* bias;
    __half* Ys = nullptr;
    int tile_m, tile_n;
    float esc = 1.f;

    if (mode == 0) {
        int idx = blockIdx.x, local;
        if (idx < 128)      { local = idx;       Ap = g_q; Bp = g_wq; bias = bq; Ys = g_pq; esc = QSC; }
        else if (idx < 384) { local = idx - 128; Ap = g_k; Bp = g_wk; bias = bk; Ys = g_pk; }
        else if (idx < 640) { local = idx - 384; Ap = g_v; Bp = g_wv; bias = bv; Ys = g_pv; }
        else if (idx < 768) { local = idx - 640; Ap = g_m; Bp = g_wk; bias = bk; Ys = g_pmk; }
        else                { local = idx - 768; Ap = g_m; Bp = g_wv; bias = bv; Ys = g_pmv; }
        tile_m = (local >> 3) * 128; tile_n = (local & 7) * 128;
    } else {
        Ap = g_o; Bp = g_wo; bias = bo;
        tile_m = ((int)blockIdx.x >> 3) * 128; tile_n = ((int)blockIdx.x & 7) * 128;
    }

    float acc[4][8][4];
    #pragma unroll
    for (int i = 0; i < 4; i++)
        #pragma unroll
        for (int j = 0; j < 8; j++)
            #pragma unroll
            for (int kx = 0; kx < 4; kx++) acc[i][j][kx] = 0.f;

    // loader: 16 chunks of 16B per thread per stage (A 1024 + B 1024 slots)
    auto issue_stage = [&](int c, int st) {
        const uint32_t sb = sbase + st * GSTAGE;
        #pragma unroll
        for (int i = 0; i < 16; i++) {
            int slot = i * 128 + t;
            int buf = slot >> 10;
            int w = slot & 1023;
            int row = w >> 3, logc = w & 7;
            const __half* src = (buf ? Bp + (size_t)(tile_n + row) * 1024
                                     : Ap + (size_t)(tile_m + row) * 1024) + c * 64 + logc * 8;
            cp_async16(sb + buf * 16384 + row * 128 + ((logc ^ (row & 7)) * 16), src);
        }
        CP_COMMIT();
    };

    issue_stage(0, 0);
    issue_stage(1, 1);

    const int q = lane >> 3, li = lane & 7;

    for (int c = 0; c < 16; c++) {
        const int st = c % 3;
        if (c < 15) CP_WAIT(1); else CP_WAIT(0);
        __syncthreads();
        if (c + 2 < 16) issue_stage(c + 2, (c + 2) % 3);

        const uint32_t Ab = sbase + st * GSTAGE;
        const uint32_t Bb = Ab + 16384;

        #pragma unroll
        for (int ks = 0; ks < 4; ks++) {
            uint32_t ah[4][4], bh[8][2];
            #pragma unroll
            for (int mf = 0; mf < 4; mf++) {
                int row = warp_m * 64 + mf * 16 + (q & 1) * 8 + li;
                int lch = (ks * 2 + (q >> 1)) ^ (row & 7);
                ldm_x4(ah[mf], Ab + row * 128 + lch * 16);
            }
            #pragma unroll
            for (int p = 0; p < 4; p++) {
                int row = warp_n * 64 + p * 16 + (q >> 1) * 8 + li;
                int lch = (ks * 2 + (q & 1)) ^ (row & 7);
                uint32_t r4[4];
                ldm_x4(r4, Bb + row * 128 + lch * 16);
                bh[p * 2][0] = r4[0]; bh[p * 2][1] = r4[1];
                bh[p * 2 + 1][0] = r4[2]; bh[p * 2 + 1][1] = r4[3];
            }
            #pragma unroll
            for (int mf = 0; mf < 4; mf++)
                #pragma unroll
                for (int nf = 0; nf < 8; nf++)
                    mma_f16(acc[mf][nf], ah[mf], bh[nf]);
        }
    }

    // epilogue
    #pragma unroll
    for (int mf = 0; mf < 4; mf++) {
        int r0 = tile_m + warp_m * 64 + mf * 16 + (lane >> 2);
        #pragma unroll
        for (int nf = 0; nf < 8; nf++) {
            int col = tile_n + warp_n * 64 + nf * 8 + (lane & 3) * 2;
            float b0 = __ldg(bias + col), b1 = __ldg(bias + col + 1);
            float v00 = (acc[mf][nf][0] + b0) * esc, v01 = (acc[mf][nf][1] + b1) * esc;
            float v10 = (acc[mf][nf][2] + b0) * esc, v11 = (acc[mf][nf][3] + b1) * esc;
            if (mode == 0) {
                *(uint32_t*)(Ys + (size_t)r0 * 1024 + col)       = pack_h2(v00, v01);
                *(uint32_t*)(Ys + (size_t)(r0 + 8) * 1024 + col) = pack_h2(v10, v11);
            } else {
                *(float2*)(out + (size_t)r0 * 1024 + col)       = make_float2(v00, v01);
                *(float2*)(out + (size_t)(r0 + 8) * 1024 + col) = make_float2(v10, v11);
            }
        }
    }
}

// ============================================================
// Flash attention: Q-tile 256 rows, 512 threads (16 warps x 16
// rows), 3-stage KV ring, streamed softmax (per-kf S->ex2->PV).
// Fixed-max, f16x2 ex2, ones-mma row sums. Grid 256 CTAs,
// 2 CTAs/SM (32 warps/SM).
// ============================================================
#define SROW 80
#define ATTN_SMEM (20480 + 3 * 10240)
__global__ __launch_bounds__(512, 2) void attn_mma()
{
    extern __shared__ char smem[];
    const uint32_t sbase = smem_u32(smem);
    const int t = threadIdx.x, wid = t >> 5, lane = t & 31;
    const int q0 = blockIdx.x * 256;
    const int bh = blockIdx.y, b = bh >> 5, h = bh & 31;
    const int qg = lane >> 3, li = lane & 7;

    auto issue_kv_nc = [&](int kt, int st) {   // 1 cp.async per thread
        const int l0 = kt * 64;
        size_t rb;
        const __half *s0, *s1;
        if (l0 < KK) { rb = (size_t)(b * KK + l0);        s0 = g_pk;  s1 = g_pv; }
        else         { rb = (size_t)(b * MM + (l0 - KK)); s0 = g_pmk; s1 = g_pmv; }
        uint32_t stb = sbase + 20480 + st * 10240;
        int tens = t >> 8;              // 0 = K, 1 = V
        int row = (t >> 2) & 63, c = t & 3;
        size_t goff = (rb + row) * EE + h * 32 + c * 8;
        cp_async16(stb + tens * 5120 + row * SROW + c * 16,
                   (tens ? s1 : s0) + goff);
    };

    // Group 0: Q (256 rows x 4 chunks) + KV tile 0
    #pragma unroll
    for (int i = 0; i < 2; i++) {
        int w2 = i * 512 + t;
        int row = w2 >> 2, c = w2 & 3;
        const __half* g = g_pq + (size_t)(b * QQ + q0 + row) * EE + h * 32 + c * 8;
        cp_async16(sbase + row * SROW + c * 16, g);
    }
    issue_kv_nc(0, 0);
    CP_COMMIT();
    issue_kv_nc(1, 1);
    CP_COMMIT();

    uint32_t qh[2][4];
    float oacc[4][4];
    #pragma unroll
    for (int i = 0; i < 4; i++)
        #pragma unroll
        for (int j = 0; j < 4; j++) oacc[i][j] = 0.f;
    float lacc[4] = {0.f, 0.f, 0.f, 0.f};
    const uint32_t onesb[2] = {0x3C003C00u, 0x3C003C00u};   // 1.0h x2

    for (int kt = 0; kt < LTOT / 64; kt++) {
        const int st = kt % 3;
        if (kt < LTOT / 64 - 1) CP_WAIT(1); else CP_WAIT(0);
        __syncthreads();
        if (kt + 2 < LTOT / 64) { issue_kv_nc(kt + 2, (kt + 2) % 3); CP_COMMIT(); }

        if (kt == 0) {
            #pragma unroll
            for (int ks = 0; ks < 2; ks++) {
                uint32_t a = sbase + (wid * 16 + (lane & 15)) * SROW + (ks * 2 + (lane >> 4)) * 16;
                ldm_x4(qh[ks], a);
            }
        }

        const uint32_t KB = sbase + 20480 + st * 10240;
        const uint32_t VB = KB + 5120;

        // ---- streamed: per p, S -> exp2 -> row-sum -> PV
        #pragma unroll
        for (int p = 0; p < 4; p++) {
            uint32_t kh[2][4];
            #pragma unroll
            for (int ks = 0; ks < 2; ks++) {
                int row = p * 16 + (qg >> 1) * 8 + li;
                uint32_t off = row * SROW + (ks * 2 + (qg & 1)) * 16;
                ldm_x4(kh[ks], KB + off);
            }
            float sl[2][4];
            #pragma unroll
            for (int j = 0; j < 4; j++) { sl[0][j] = 0.f; sl[1][j] = 0.f; }
            #pragma unroll
            for (int ks = 0; ks < 2; ks++) {
                mma_f16(sl[0], qh[ks], kh[ks]);
                mma_f16(sl[1], qh[ks], kh[ks] + 2);
            }

            uint32_t ph[4];
            ph[0] = h2ex2(pack_h2(sl[0][0], sl[0][1]));
            ph[1] = h2ex2(pack_h2(sl[0][2], sl[0][3]));
            ph[2] = h2ex2(pack_h2(sl[1][0], sl[1][1]));
            ph[3] = h2ex2(pack_h2(sl[1][2], sl[1][3]));

            mma_f16(lacc, ph, onesb);   // row sums

            uint32_t vh[4][2];
            #pragma unroll
            for (int x = 0; x < 2; x++) {
                int key = p * 16 + (qg & 1) * 8 + li;
                uint32_t off = key * SROW + (x * 2 + (qg >> 1)) * 16;
                uint32_t r4[4];
                ldm_x4t(r4, VB + off);
                vh[x * 2][0] = r4[0]; vh[x * 2][1] = r4[1];
                vh[x * 2 + 1][0] = r4[2]; vh[x * 2 + 1][1] = r4[3];
            }
            #pragma unroll
            for (int nf = 0; nf < 4; nf++)
                mma_f16(oacc[nf], ph, vh[nf]);
        }
    }

    // ---- epilogue: normalize + single fp16 write
    float inv0 = 1.f / lacc[0], inv1 = 1.f / lacc[2];
    size_t row0 = (size_t)(b * QQ + q0 + wid * 16 + (lane >> 2)) * EE;
    size_t row1 = row0 + 8 * EE;
    int colb = h * 32 + (lane & 3) * 2;
    #pragma unroll
    for (int nf = 0; nf < 4; nf++) {
        int cc = colb + nf * 8;
        *(uint32_t*)(g_o + row0 + cc) = pack_h2(oacc[nf][0] * inv0, oacc[nf][1] * inv0);
        *(uint32_t*)(g_o + row1 + cc) = pack_h2(oacc[nf][2] * inv1, oacc[nf][3] * inv1);
    }
}

// ============================================================
// launch
// ============================================================
extern "C" void kernel_launch(void* const* d_in, const int* in_sizes, int n_in,
                              void* d_out, int out_size)
{
    const float* query  = (const float*)d_in[0];
    const float* key    = (const float*)d_in[1];
    const float* value  = (const float*)d_in[2];
    const float* memory = (const float*)d_in[3];
    const float* Wq = (const float*)d_in[4];
    const float* bq = (const float*)d_in[5];
    const float* Wk = (const float*)d_in[6];
    const float* bk = (const float*)d_in[7];
    const float* Wv = (const float*)d_in[8];
    const float* bv = (const float*)d_in[9];
    const float* Wo = (const float*)d_in[10];
    const float* bo = (const float*)d_in[11];
    float* out = (float*)d_out;

    cudaFuncSetAttribute(gemm_all, cudaFuncAttributeMaxDynamicSharedMemorySize, GEMM_SMEM);
    cudaFuncSetAttribute(attn_mma, cudaFuncAttributeMaxDynamicSharedMemorySize, ATTN_SMEM);

    // 1. All fp32 -> fp16 conversions (one launch)
    split_all<<<16384, 256>>>(query, key, value, memory, Wq, Wk, Wv, Wo);

    // 2. All 5 projection GEMMs (one merged launch, 896 tiles of 128x128)
    gemm_all<<<896, 128, GEMM_SMEM>>>(0, bq, bk, bv, nullptr, nullptr);

    // 3. Attention: grid (Q/256 = 4, B*H = 64) -> 256 CTAs, single wave
    attn_mma<<<dim3(4, 64), 512, ATTN_SMEM>>>();

    // 4. Output projection -> fp32 out (128 tiles of 128x128)
    gemm_all<<<128, 128, GEMM_SMEM>>>(1, nullptr, nullptr, nullptr, bo, out);
}

// round 16
// speedup vs baseline: 1.1360x; 1.0135x over previous
#include <cuda_runtime.h>
#include <cuda.h>
#include <cuda_fp16.h>
#include <cstdint>
#include <math.h>

// Problem constants
#define BB 2
#define QQ 1024
#define KK 2048
#define MM 1024
#define EE 1024
#define HH 32
#define HD 32
#define LTOT (KK + MM)   // 3072
#define QSC   (0.17677669529663687f * 1.4426950408889634f)   // SCALE * log2(e)

// -------- fp16 scratch: input splits (all single) --------
__device__ __half g_q[BB*QQ*EE];
__device__ __half g_k[BB*KK*EE];
__device__ __half g_v[BB*KK*EE];
__device__ __half g_m[BB*MM*EE];
__device__ __half g_wq[EE*EE];
__device__ __half g_wk[EE*EE];
__device__ __half g_wv[EE*EE];
__device__ __half g_wo[EE*EE];

// -------- fp16 scratch: projected tensors (all single) --------
__device__ __half g_pq[BB*QQ*EE];     // pre-scaled by QSC
__device__ __half g_pk[BB*KK*EE];
__device__ __half g_pv[BB*KK*EE];
__device__ __half g_pmk[BB*MM*EE];
__device__ __half g_pmv[BB*MM*EE];
__device__ __half g_o[BB*QQ*EE];

// ============================================================
// PTX helpers
// ============================================================
__device__ __forceinline__ uint32_t smem_u32(const void* p) {
    uint32_t a;
    asm("{ .reg .u64 t; cvta.to.shared.u64 t, %1; cvt.u32.u64 %0, t; }" : "=r"(a) : "l"(p));
    return a;
}

__device__ __forceinline__ void cp_async16(uint32_t saddr, const void* gptr) {
    asm volatile("cp.async.cg.shared.global [%0], [%1], 16;" :: "r"(saddr), "l"(gptr) : "memory");
}
#define CP_COMMIT() asm volatile("cp.async.commit_group;" ::: "memory")
#define CP_WAIT(n)  asm volatile("cp.async.wait_group %0;" :: "n"(n) : "memory")

#define MBAR_INIT(mb, c)   asm volatile("mbarrier.init.shared.b64 [%0], %1;" :: "r"(mb), "r"((uint32_t)(c)) : "memory")
#define MBAR_EXPECT(mb, n) asm volatile("mbarrier.arrive.expect_tx.shared.b64 _, [%0], %1;" :: "r"(mb), "r"((uint32_t)(n)) : "memory")

__device__ __forceinline__ void mbar_wait(uint32_t mb, uint32_t parity) {
    asm volatile(
        "{\n\t.reg .pred P1;\n\t"
        "W_%=:\n\t"
        "mbarrier.try_wait.parity.acquire.cta.shared::cta.b64 P1, [%0], %1, 0x989680;\n\t"
        "@P1 bra.uni D_%=;\n\t"
        "bra.uni W_%=;\n\t"
        "D_%=:\n\t}"
        :: "r"(mb), "r"(parity) : "memory");
}

__device__ __forceinline__ void tma2d(uint32_t smem_addr, const void* map, int x, int y, uint32_t mbar) {
    asm volatile(
        "cp.async.bulk.tensor.2d.shared::cta.global.tile.mbarrier::complete_tx::bytes "
        "[%0], [%1, {%2, %3}], [%4];"
        :: "r"(smem_addr), "l"(map), "r"(x), "r"(y), "r"(mbar) : "memory");
}

__device__ __forceinline__ void ldm_x4(uint32_t* r, uint32_t addr) {
    asm volatile("ldmatrix.sync.aligned.m8n8.x4.shared.b16 {%0,%1,%2,%3}, [%4];"
                 : "=r"(r[0]), "=r"(r[1]), "=r"(r[2]), "=r"(r[3]) : "r"(addr));
}
__device__ __forceinline__ void ldm_x4t(uint32_t* r, uint32_t addr) {
    asm volatile("ldmatrix.sync.aligned.m8n8.x4.trans.shared.b16 {%0,%1,%2,%3}, [%4];"
                 : "=r"(r[0]), "=r"(r[1]), "=r"(r[2]), "=r"(r[3]) : "r"(addr));
}

__device__ __forceinline__ void mma_f16(float* d, const uint32_t* a, const uint32_t* b) {
    asm volatile(
        "mma.sync.aligned.m16n8k16.row.col.f32.f16.f16.f32 "
        "{%0,%1,%2,%3}, {%4,%5,%6,%7}, {%8,%9}, {%0,%1,%2,%3};"
        : "+f"(d[0]), "+f"(d[1]), "+f"(d[2]), "+f"(d[3])
        : "r"(a[0]), "r"(a[1]), "r"(a[2]), "r"(a[3]), "r"(b[0]), "r"(b[1]));
}

__device__ __forceinline__ uint32_t h2ex2(uint32_t x) {
    uint32_t y;
    asm("ex2.approx.f16x2 %0, %1;" : "=r"(y) : "r"(x));
    return y;
}

__device__ __forceinline__ uint32_t pack_h2(float x0, float x1) {
    __half2 h = __floats2half2_rn(x0, x1);
    return *reinterpret_cast<uint32_t*>(&h);
}

// ============================================================
// Merged fp32 -> fp16 split (all tensors single fp16).
// ============================================================
__global__ __launch_bounds__(256) void split_all(
    const float* __restrict__ q, const float* __restrict__ k,
    const float* __restrict__ v, const float* __restrict__ m,
    const float* __restrict__ wq, const float* __restrict__ wk,
    const float* __restrict__ wv, const float* __restrict__ wo)
{
    size_t i4 = ((size_t)blockIdx.x * 256 + threadIdx.x) * 4;
    const float* src; __half* dst; size_t off;
    if      (i4 < 2097152)  { src = q;  dst = g_q;  off = i4; }
    else if (i4 < 6291456)  { src = k;  dst = g_k;  off = i4 - 2097152; }
    else if (i4 < 10485760) { src = v;  dst = g_v;  off = i4 - 6291456; }
    else if (i4 < 12582912) { src = m;  dst = g_m;  off = i4 - 10485760; }
    else if (i4 < 13631488) { src = wq; dst = g_wq; off = i4 - 12582912; }
    else if (i4 < 14680064) { src = wk; dst = g_wk; off = i4 - 13631488; }
    else if (i4 < 15728640) { src = wv; dst = g_wv; off = i4 - 14680064; }
    else                    { src = wo; dst = g_wo; off = i4 - 15728640; }
    float4 x = *(const float4*)(src + off);
    *(uint2*)(dst + off) = make_uint2(pack_h2(x.x, x.y), pack_h2(x.z, x.w));
}

// ============================================================
// HMMA GEMM (NT): all single fp16, 1-pass. Tile 128x128,
// K-chunk 64, 128 threads (4 warps 2x2, warp tile 64x64),
// 3-stage TMA pipeline (2 bulk loads/stage instead of 2048
// cp.async ops -> removes the LDGSTS issue-rate cap).
// Smem: [0:24) mbar x3, stages at 1024 (32KB each: A 16KB + B 16KB).
// mode 0: merged 5-projection launch (896 tiles, fp16 out).
// mode 1: out-proj (128 tiles, fp32 out).
// ============================================================
#define GSTAGE 32768
#define GEMM_SMEM (1024 + 3 * GSTAGE)
__global__ __launch_bounds__(128, 2) void gemm_all(
    int mode,
    const __grid_constant__ CUtensorMap mQ,
    const __grid_constant__ CUtensorMap mK,
    const __grid_constant__ CUtensorMap mV,
    const __grid_constant__ CUtensorMap mM,
    const __grid_constant__ CUtensorMap mWq,
    const __grid_constant__ CUtensorMap mWk,
    const __grid_constant__ CUtensorMap mWv,
    const float* __restrict__ bq, const float* __restrict__ bk,
    const float* __restrict__ bv, float* __restrict__ out)
{
    extern __shared__ char smem[];
    const uint32_t sbase = smem_u32(smem);
    const int t = threadIdx.x, wid = t >> 5, lane = t & 31;
    const int warp_m = wid & 1, warp_n = wid >> 1;

    const CUtensorMap *Am, *Bm;
    const float* bias;
    __half* Ys = nullptr;
    int tile_m, tile_n;
    float esc = 1.f;

    if (mode == 0) {
        int idx = blockIdx.x, local;
        if (idx < 128)      { local = idx;       Am = &mQ; Bm = &mWq; bias = bq; Ys = g_pq; esc = QSC; }
        else if (idx < 384) { local = idx - 128; Am = &mK; Bm = &mWk; bias = bk; Ys = g_pk; }
        else if (idx < 640) { local = idx - 384; Am = &mV; Bm = &mWv; bias = bv; Ys = g_pv; }
        else if (idx < 768) { local = idx - 640; Am = &mM; Bm = &mWk; bias = bk; Ys = g_pmk; }
        else                { local = idx - 768; Am = &mM; Bm = &mWv; bias = bv; Ys = g_pmv; }
        tile_m = (local >> 3) * 128; tile_n = (local & 7) * 128;
    } else {
        Am = &mQ; Bm = &mWq; bias = bq;   // mode 1: o-map / wo-map passed in these slots
        tile_m = ((int)blockIdx.x >> 3) * 128; tile_n = ((int)blockIdx.x & 7) * 128;
    }

    if (t == 0) {
        MBAR_INIT(sbase + 0, 1);
        MBAR_INIT(sbase + 8, 1);
        MBAR_INIT(sbase + 16, 1);
    }
    __syncthreads();

    auto issue = [&](int c, int st) {
        if (t == 0) {
            uint32_t mb = sbase + st * 8;
            MBAR_EXPECT(mb, GSTAGE);
            uint32_t sb = sbase + 1024 + st * GSTAGE;
            tma2d(sb,         (const void*)Am, c * 64, tile_m, mb);
            tma2d(sb + 16384, (const void*)Bm, c * 64, tile_n, mb);
        }
    };

    float acc[4][8][4];
    #pragma unroll
    for (int i = 0; i < 4; i++)
        #pragma unroll
        for (int j = 0; j < 8; j++)
            #pragma unroll
            for (int kx = 0; kx < 4; kx++) acc[i][j][kx] = 0.f;

    issue(0, 0);
    issue(1, 1);

    const int q = lane >> 3, li = lane & 7;

    for (int c = 0; c < 16; c++) {
        const int st = c % 3;
        mbar_wait(sbase + st * 8, (uint32_t)((c / 3) & 1));
        __syncthreads();
        if (c + 2 < 16) issue(c + 2, (c + 2) % 3);

        const uint32_t Ab = sbase + 1024 + st * GSTAGE;
        const uint32_t Bb = Ab + 16384;

        #pragma unroll
        for (int ks = 0; ks < 4; ks++) {
            uint32_t ah[4][4], bh[8][2];
            #pragma unroll
            for (int mf = 0; mf < 4; mf++) {
                int row = warp_m * 64 + mf * 16 + (q & 1) * 8 + li;
                int lch = (ks * 2 + (q >> 1)) ^ (row & 7);
                ldm_x4(ah[mf], Ab + row * 128 + lch * 16);
            }
            #pragma unroll
            for (int p = 0; p < 4; p++) {
                int row = warp_n * 64 + p * 16 + (q >> 1) * 8 + li;
                int lch = (ks * 2 + (q & 1)) ^ (row & 7);
                uint32_t r4[4];
                ldm_x4(r4, Bb + row * 128 + lch * 16);
                bh[p * 2][0] = r4[0]; bh[p * 2][1] = r4[1];
                bh[p * 2 + 1][0] = r4[2]; bh[p * 2 + 1][1] = r4[3];
            }
            #pragma unroll
            for (int mf = 0; mf < 4; mf++)
                #pragma unroll
                for (int nf = 0; nf < 8; nf++)
                    mma_f16(acc[mf][nf], ah[mf], bh[nf]);
        }
    }

    // epilogue
    #pragma unroll
    for (int mf = 0; mf < 4; mf++) {
        int r0 = tile_m + warp_m * 64 + mf * 16 + (lane >> 2);
        #pragma unroll
        for (int nf = 0; nf < 8; nf++) {
            int col = tile_n + warp_n * 64 + nf * 8 + (lane & 3) * 2;
            float b0 = __ldg(bias + col), b1 = __ldg(bias + col + 1);
            float v00 = (acc[mf][nf][0] + b0) * esc, v01 = (acc[mf][nf][1] + b1) * esc;
            float v10 = (acc[mf][nf][2] + b0) * esc, v11 = (acc[mf][nf][3] + b1) * esc;
            if (mode == 0) {
                *(uint32_t*)(Ys + (size_t)r0 * 1024 + col)       = pack_h2(v00, v01);
                *(uint32_t*)(Ys + (size_t)(r0 + 8) * 1024 + col) = pack_h2(v10, v11);
            } else {
                *(float2*)(out + (size_t)r0 * 1024 + col)       = make_float2(v00, v01);
                *(float2*)(out + (size_t)(r0 + 8) * 1024 + col) = make_float2(v10, v11);
            }
        }
    }
}

// ============================================================
// Flash attention: Q-tile 256 rows, 512 threads (16 warps x 16
// rows), 3-stage KV ring, streamed softmax (per-p S->ex2->PV).
// Fixed-max, f16x2 ex2, ones-mma row sums. (Unchanged from R15.)
// ============================================================
#define SROW 80
#define ATTN_SMEM (20480 + 3 * 10240)
__global__ __launch_bounds__(512, 2) void attn_mma()
{
    extern __shared__ char smem[];
    const uint32_t sbase = smem_u32(smem);
    const int t = threadIdx.x, wid = t >> 5, lane = t & 31;
    const int q0 = blockIdx.x * 256;
    const int bh = blockIdx.y, b = bh >> 5, h = bh & 31;
    const int qg = lane >> 3, li = lane & 7;

    auto issue_kv_nc = [&](int kt, int st) {
        const int l0 = kt * 64;
        size_t rb;
        const __half *s0, *s1;
        if (l0 < KK) { rb = (size_t)(b * KK + l0);        s0 = g_pk;  s1 = g_pv; }
        else         { rb = (size_t)(b * MM + (l0 - KK)); s0 = g_pmk; s1 = g_pmv; }
        uint32_t stb = sbase + 20480 + st * 10240;
        int tens = t >> 8;
        int row = (t >> 2) & 63, c = t & 3;
        size_t goff = (rb + row) * EE + h * 32 + c * 8;
        cp_async16(stb + tens * 5120 + row * SROW + c * 16,
                   (tens ? s1 : s0) + goff);
    };

    #pragma unroll
    for (int i = 0; i < 2; i++) {
        int w2 = i * 512 + t;
        int row = w2 >> 2, c = w2 & 3;
        const __half* g = g_pq + (size_t)(b * QQ + q0 + row) * EE + h * 32 + c * 8;
        cp_async16(sbase + row * SROW + c * 16, g);
    }
    issue_kv_nc(0, 0);
    CP_COMMIT();
    issue_kv_nc(1, 1);
    CP_COMMIT();

    uint32_t qh[2][4];
    float oacc[4][4];
    #pragma unroll
    for (int i = 0; i < 4; i++)
        #pragma unroll
        for (int j = 0; j < 4; j++) oacc[i][j] = 0.f;
    float lacc[4] = {0.f, 0.f, 0.f, 0.f};
    const uint32_t onesb[2] = {0x3C003C00u, 0x3C003C00u};

    for (int kt = 0; kt < LTOT / 64; kt++) {
        const int st = kt % 3;
        if (kt < LTOT / 64 - 1) CP_WAIT(1); else CP_WAIT(0);
        __syncthreads();
        if (kt + 2 < LTOT / 64) { issue_kv_nc(kt + 2, (kt + 2) % 3); CP_COMMIT(); }

        if (kt == 0) {
            #pragma unroll
            for (int ks = 0; ks < 2; ks++) {
                uint32_t a = sbase + (wid * 16 + (lane & 15)) * SROW + (ks * 2 + (lane >> 4)) * 16;
                ldm_x4(qh[ks], a);
            }
        }

        const uint32_t KB = sbase + 20480 + st * 10240;
        const uint32_t VB = KB + 5120;

        #pragma unroll
        for (int p = 0; p < 4; p++) {
            uint32_t kh[2][4];
            #pragma unroll
            for (int ks = 0; ks < 2; ks++) {
                int row = p * 16 + (qg >> 1) * 8 + li;
                uint32_t off = row * SROW + (ks * 2 + (qg & 1)) * 16;
                ldm_x4(kh[ks], KB + off);
            }
            float sl[2][4];
            #pragma unroll
            for (int j = 0; j < 4; j++) { sl[0][j] = 0.f; sl[1][j] = 0.f; }
            #pragma unroll
            for (int ks = 0; ks < 2; ks++) {
                mma_f16(sl[0], qh[ks], kh[ks]);
                mma_f16(sl[1], qh[ks], kh[ks] + 2);
            }

            uint32_t ph[4];
            ph[0] = h2ex2(pack_h2(sl[0][0], sl[0][1]));
            ph[1] = h2ex2(pack_h2(sl[0][2], sl[0][3]));
            ph[2] = h2ex2(pack_h2(sl[1][0], sl[1][1]));
            ph[3] = h2ex2(pack_h2(sl[1][2], sl[1][3]));

            mma_f16(lacc, ph, onesb);

            uint32_t vh[4][2];
            #pragma unroll
            for (int x = 0; x < 2; x++) {
                int key = p * 16 + (qg & 1) * 8 + li;
                uint32_t off = key * SROW + (x * 2 + (qg >> 1)) * 16;
                uint32_t r4[4];
                ldm_x4t(r4, VB + off);
                vh[x * 2][0] = r4[0]; vh[x * 2][1] = r4[1];
                vh[x * 2 + 1][0] = r4[2]; vh[x * 2 + 1][1] = r4[3];
            }
            #pragma unroll
            for (int nf = 0; nf < 4; nf++)
                mma_f16(oacc[nf], ph, vh[nf]);
        }
    }

    float inv0 = 1.f / lacc[0], inv1 = 1.f / lacc[2];
    size_t row0 = (size_t)(b * QQ + q0 + wid * 16 + (lane >> 2)) * EE;
    size_t row1 = row0 + 8 * EE;
    int colb = h * 32 + (lane & 3) * 2;
    #pragma unroll
    for (int nf = 0; nf < 4; nf++) {
        int cc = colb + nf * 8;
        *(uint32_t*)(g_o + row0 + cc) = pack_h2(oacc[nf][0] * inv0, oacc[nf][1] * inv0);
        *(uint32_t*)(g_o + row1 + cc) = pack_h2(oacc[nf][2] * inv1, oacc[nf][3] * inv1);
    }
}

// ============================================================
// host: tensor-map construction (driver API via runtime entry point)
// ============================================================
typedef CUresult (CUDAAPI *EncodeTiledFn)(
    CUtensorMap*, CUtensorMapDataType, cuuint32_t, void*,
    const cuuint64_t*, const cuuint64_t*, const cuuint32_t*, const cuuint32_t*,
    CUtensorMapInterleave, CUtensorMapSwizzle, CUtensorMapL2promotion,
    CUtensorMapFloatOOBfill);

static void make_map(EncodeTiledFn enc, CUtensorMap* m, void* ptr, unsigned long long rows) {
    cuuint64_t dims[2]    = {1024ull, rows};
    cuuint64_t strides[1] = {2048ull};
    cuuint32_t box[2]     = {64u, 128u};
    cuuint32_t es[2]      = {1u, 1u};
    enc(m, CU_TENSOR_MAP_DATA_TYPE_FLOAT16, 2, ptr, dims, strides, box, es,
        CU_TENSOR_MAP_INTERLEAVE_NONE, CU_TENSOR_MAP_SWIZZLE_128B,
        CU_TENSOR_MAP_L2_PROMOTION_L2_128B, CU_TENSOR_MAP_FLOAT_OOB_FILL_NONE);
}

// ============================================================
// launch
// ============================================================
extern "C" void kernel_launch(void* const* d_in, const int* in_sizes, int n_in,
                              void* d_out, int out_size)
{
    const float* query  = (const float*)d_in[0];
    const float* key    = (const float*)d_in[1];
    const float* value  = (const float*)d_in[2];
    const float* memory = (const float*)d_in[3];
    const float* Wq = (const float*)d_in[4];
    const float* bq = (const float*)d_in[5];
    const float* Wk = (const float*)d_in[6];
    const float* bk = (const float*)d_in[7];
    const float* Wv = (const float*)d_in[8];
    const float* bv = (const float*)d_in[9];
    const float* Wo = (const float*)d_in[10];
    const float* bo = (const float*)d_in[11];
    float* out = (float*)d_out;

    // tensor maps for TMA (device symbol addresses are fixed; recompute each call)
    EncodeTiledFn enc = nullptr;
    {
        void* fn = nullptr;
        cudaDriverEntryPointQueryResult st;
        cudaGetDriverEntryPoint("cuTensorMapEncodeTiled", &fn, cudaEnableDefault, &st);
        enc = (EncodeTiledFn)fn;
    }
    void *pq_, *pk_, *pv_, *pm_, *pwq_, *pwk_, *pwv_, *pwo_, *po_;
    cudaGetSymbolAddress(&pq_,  g_q);
    cudaGetSymbolAddress(&pk_,  g_k);
    cudaGetSymbolAddress(&pv_,  g_v);
    cudaGetSymbolAddress(&pm_,  g_m);
    cudaGetSymbolAddress(&pwq_, g_wq);
    cudaGetSymbolAddress(&pwk_, g_wk);
    cudaGetSymbolAddress(&pwv_, g_wv);
    cudaGetSymbolAddress(&pwo_, g_wo);
    cudaGetSymbolAddress(&po_,  g_o);

    CUtensorMap tQ, tK, tV, tM, tWq, tWk, tWv, tO, tWo;
    make_map(enc, &tQ,  pq_,  2048);
    make_map(enc, &tK,  pk_,  4096);
    make_map(enc, &tV,  pv_,  4096);
    make_map(enc, &tM,  pm_,  2048);
    make_map(enc, &tWq, pwq_, 1024);
    make_map(enc, &tWk, pwk_, 1024);
    make_map(enc, &tWv, pwv_, 1024);
    make_map(enc, &tO,  po_,  2048);
    make_map(enc, &tWo, pwo_, 1024);

    cudaFuncSetAttribute(gemm_all, cudaFuncAttributeMaxDynamicSharedMemorySize, GEMM_SMEM);
    cudaFuncSetAttribute(attn_mma, cudaFuncAttributeMaxDynamicSharedMemorySize, ATTN_SMEM);

    // 1. All fp32 -> fp16 conversions (one launch)
    split_all<<<16384, 256>>>(query, key, value, memory, Wq, Wk, Wv, Wo);

    // 2. All 5 projection GEMMs (one merged TMA launch, 896 tiles of 128x128)
    gemm_all<<<896, 128, GEMM_SMEM>>>(0, tQ, tK, tV, tM, tWq, tWk, tWv,
                                      bq, bk, bv, nullptr);

    // 3. Attention: grid (Q/256 = 4, B*H = 64) -> 256 CTAs, single wave
    attn_mma<<<dim3(4, 64), 512, ATTN_SMEM>>>();

    // 4. Output projection -> fp32 out (128 tiles of 128x128)
    gemm_all<<<128, 128, GEMM_SMEM>>>(1, tO, tK, tV, tM, tWo, tWk, tWv,
                                      bo, bk, bv, out);
}